// round 13
// baseline (speedup 1.0000x reference)
#include <cuda_runtime.h>

#define TT   2048
#define HB   128
#define NL   3
#define GCTA 32      // H-CTAs per layer
#define NJ   4       // hidden j per H-CTA
#define NR   16      // gate rows per H-CTA
#define XCTA 16      // X-CTAs per layer (layers 1,2)
#define XR   32      // gate rows per X-CTA

// h history, PAIR-PACKED: (l, slot, j, b) at ((l*(TT+1)+slot)*64 + (j>>1))*256 + b*2 + (j&1)
__device__ __align__(16) float g_H[(size_t)NL * (TT + 1) * HB * HB];
// Partial ih sums: P(l,t,R,b) = ((l*TT+t)*512 + R)*128 + b.  l=0 precomputed in setup.
__device__ __align__(16) float g_P[(size_t)NL * TT * 512 * HB];
// hh weights per H-CTA: [l][g][r(16)][k(128)], r = q*4+jj <-> R = q*128 + g*4 + jj
__device__ float g_WpH[NL * GCTA * NR * 128];
// ih weights per X-CTA (layers 1,2): [xl][xg][r(32)][k(128)], r=q*8+j <-> R = q*128 + xg*8 + j
__device__ float g_WpX[2 * XCTA * XR * 128];
__device__ float g_bias[NL * GCTA * NR];
__device__ __align__(128) int g_flagsH[NL * GCTA];   // steps completed per H-CTA
__device__ __align__(128) int g_flagsX[2 * XCTA];    // steps completed per X-CTA

typedef unsigned long long ull;

__device__ __forceinline__ ull pk2(float lo, float hi) {
    ull r; asm("mov.b64 %0,{%1,%2};" : "=l"(r) : "f"(lo), "f"(hi)); return r;
}
__device__ __forceinline__ void upk2(ull v, float& lo, float& hi) {
    asm("mov.b64 {%0,%1},%2;" : "=f"(lo), "=f"(hi) : "l"(v));
}
__device__ __forceinline__ ull ffma2(ull a, ull b, ull c) {
    ull d; asm("fma.rn.f32x2 %0,%1,%2,%3;" : "=l"(d) : "l"(a), "l"(b), "l"(c));
    return d;
}
__device__ __forceinline__ int ldacq(const int* p) {
    int v; asm volatile("ld.acquire.gpu.global.b32 %0,[%1];" : "=r"(v) : "l"(p) : "memory");
    return v;
}
__device__ __forceinline__ void strel(int* p, int v) {
    asm volatile("st.release.gpu.global.b32 [%0],%1;" :: "l"(p), "r"(v) : "memory");
}
__device__ __forceinline__ float sigf(float x) {
    return __fdividef(1.0f, 1.0f + __expf(-x));
}
__device__ __forceinline__ float tanhf_fast(float x) {
    return __fdividef(2.0f, 1.0f + __expf(-2.0f * x)) - 1.0f;
}

// ============ setup ============
// blocks [0,96): WpH+bias; [96,128): WpX; [128,128+TT): P0(t); then 3 h-zero; 1 flag-zero
__global__ void setup_kernel(
    const float* __restrict__ x,
    const float* __restrict__ Wih0, const float* __restrict__ Whh0,
    const float* __restrict__ bih0, const float* __restrict__ bhh0,
    const float* __restrict__ Wih1, const float* __restrict__ Whh1,
    const float* __restrict__ bih1, const float* __restrict__ bhh1,
    const float* __restrict__ Wih2, const float* __restrict__ Whh2,
    const float* __restrict__ bih2, const float* __restrict__ bhh2)
{
    int blk = blockIdx.x, tid = threadIdx.x;
    if (blk < NL * GCTA) {
        int l = blk / GCTA, g = blk % GCTA;
        const float* Whh = (l == 0) ? Whh0 : ((l == 1) ? Whh1 : Whh2);
        const float* bih = (l == 0) ? bih0 : ((l == 1) ? bih1 : bih2);
        const float* bhh = (l == 0) ? bhh0 : ((l == 1) ? bhh1 : bhh2);
        for (int idx = tid; idx < NR * 128; idx += blockDim.x) {
            int r = idx >> 7, k = idx & 127;
            int R = (r >> 2) * 128 + g * NJ + (r & 3);
            g_WpH[(l * GCTA + g) * NR * 128 + idx] = Whh[R * 128 + k];
        }
        if (tid < NR) {
            int R = (tid >> 2) * 128 + g * NJ + (tid & 3);
            g_bias[(l * GCTA + g) * NR + tid] = bih[R] + bhh[R];
        }
    } else if (blk < NL * GCTA + 2 * XCTA) {
        int xi = blk - NL * GCTA;
        int xl = xi >> 4, xg = xi & 15;                 // xl 0->layer1, 1->layer2
        const float* Wih = (xl == 0) ? Wih1 : Wih2;
        for (int idx = tid; idx < XR * 128; idx += blockDim.x) {
            int r = idx >> 7, k = idx & 127;
            int R = (r >> 3) * 128 + xg * 8 + (r & 7);
            g_WpX[(xl * XCTA + xg) * XR * 128 + idx] = Wih[R * 128 + k];
        }
    } else if (blk < NL * GCTA + 2 * XCTA + TT) {
        // P0[t][R][b] = sum_i Wih0[R][i] * x[b][t][i]
        int t = blk - NL * GCTA - 2 * XCTA;
        __shared__ float ws[512 * 6];
        __shared__ float xs[HB * 6];
        for (int i = tid; i < 512 * 6; i += blockDim.x) ws[i] = Wih0[i];
        for (int i = tid; i < HB * 6; i += blockDim.x) {
            int b = i / 6, ii = i % 6;
            xs[i] = x[((size_t)b * TT + t) * 6 + ii];
        }
        __syncthreads();
        float* P0 = g_P + (size_t)t * 512 * HB;
        for (int r = tid; r < 512; r += blockDim.x) {
            float w0 = ws[r*6+0], w1 = ws[r*6+1], w2 = ws[r*6+2];
            float w3 = ws[r*6+3], w4 = ws[r*6+4], w5 = ws[r*6+5];
            for (int b = 0; b < HB; b++) {
                const float* xb = xs + b * 6;
                P0[r * HB + b] = w0*xb[0] + w1*xb[1] + w2*xb[2]
                               + w3*xb[3] + w4*xb[4] + w5*xb[5];
            }
        }
    } else if (blk < NL * GCTA + 2 * XCTA + TT + NL) {
        size_t base = (size_t)(blk - NL * GCTA - 2 * XCTA - TT) * (TT + 1) * HB * HB;
        for (int i = tid; i < HB * HB; i += blockDim.x) g_H[base + i] = 0.0f;
    } else {
        if (tid < NL * GCTA) g_flagsH[tid] = 0;
        if (tid < 2 * XCTA)  g_flagsX[tid] = 0;
    }
}

// ---- H hh-GEMM: 16 cols [S,S+16), 16 rows, 2 batch cols (b0, b0+32), pair-packed src
__device__ __forceinline__ void gemmH(const float* __restrict__ src,
                                      const float* __restrict__ Wsm,
                                      int S, int b0, ull* acc /*32*/)
{
    const float2* f2 = reinterpret_cast<const float2*>(src);
    #pragma unroll
    for (int kk = 0; kk < 16; kk += 4) {
        int jp = (S + kk) >> 1;
        float2 a01 = __ldcg(f2 + jp * 128 + b0);
        float2 a23 = __ldcg(f2 + (jp + 1) * 128 + b0);
        float2 e01 = __ldcg(f2 + jp * 128 + b0 + 32);
        float2 e23 = __ldcg(f2 + (jp + 1) * 128 + b0 + 32);
        ull h01 = pk2(a01.x, a01.y), h23 = pk2(a23.x, a23.y);
        ull g01 = pk2(e01.x, e01.y), g23 = pk2(e23.x, e23.y);
        const float* wrow = Wsm + S + kk;
        #pragma unroll
        for (int r = 0; r < NR; r++) {
            ulonglong2 w = *(const ulonglong2*)(wrow + r * 128);
            acc[r]      = ffma2(w.x, h01, acc[r]);
            acc[r]      = ffma2(w.y, h23, acc[r]);
            acc[NR + r] = ffma2(w.x, g01, acc[NR + r]);
            acc[NR + r] = ffma2(w.y, g23, acc[NR + r]);
        }
    }
}

// ---- H body: 96 CTAs, 512 thr, warp = kq(8 x 16cols of K=128) * bg(2)
template<int L>
__device__ __forceinline__ void h_run(int g, float* Wsm, float* RD, float* bsm)
{
    const int tid  = threadIdx.x;
    const int lane = tid & 31;
    const int warp = tid >> 5;
    const int bg   = warp & 1;
    const int kq   = warp >> 1;
    const int b0   = bg * 64 + lane;
    const int jj   = tid >> 7;
    const int be   = tid & 127;
    const int jrow = g * NJ + jj;

    for (int i = tid; i < NR * 128; i += 512)
        Wsm[i] = g_WpH[(L * GCTA + g) * NR * 128 + i];
    if (tid < NR) bsm[tid] = g_bias[(L * GCTA + g) * NR + tid];
    __syncthreads();

    float c = 0.0f;

    for (int t = 0; t < TT; t++) {
        if (warp == 0) {
            const int* own = g_flagsH + L * GCTA;
            for (;;) {
                int bad = (ldacq(own + lane) < t) ? 1 : 0;
                if (L > 0 && lane == 0)
                    bad |= (ldacq(g_flagsX + (L - 1) * XCTA + (g >> 1)) < t + 1);
                if (__ballot_sync(0xffffffffu, bad) == 0u) break;
            }
        }
        __syncthreads();

        // prefetch ih partials (needed only in epilogue)
        const float* Pb = g_P + ((size_t)L * TT + t) * 512 * HB;
        float p0 = __ldcg(Pb + (0 * 128 + jrow) * HB + be);
        float p1 = __ldcg(Pb + (1 * 128 + jrow) * HB + be);
        float p2 = __ldcg(Pb + (2 * 128 + jrow) * HB + be);
        float p3 = __ldcg(Pb + (3 * 128 + jrow) * HB + be);

        const float* SB = g_H + (size_t)(L * (TT + 1) + t) * HB * HB;
        ull acc[2 * NR];
        #pragma unroll
        for (int r = 0; r < 2 * NR; r++) acc[r] = 0ULL;
        gemmH(SB, Wsm, kq * 16, b0, acc);

        #pragma unroll
        for (int r = 0; r < NR; r++) {
            float lo, hi; upk2(acc[r], lo, hi);
            RD[(kq * NR + r) * HB + b0] = lo + hi;
            upk2(acc[NR + r], lo, hi);
            RD[(kq * NR + r) * HB + b0 + 32] = lo + hi;
        }
        __syncthreads();

        // epilogue: all 512 threads, one (jj, be)
        float v0 = bsm[0 * 4 + jj] + p0, v1 = bsm[1 * 4 + jj] + p1;
        float v2 = bsm[2 * 4 + jj] + p2, v3 = bsm[3 * 4 + jj] + p3;
        #pragma unroll
        for (int q2 = 0; q2 < 8; q2++) {
            v0 += RD[(q2 * NR + 0 * 4 + jj) * HB + be];
            v1 += RD[(q2 * NR + 1 * 4 + jj) * HB + be];
            v2 += RD[(q2 * NR + 2 * 4 + jj) * HB + be];
            v3 += RD[(q2 * NR + 3 * 4 + jj) * HB + be];
        }
        float iv = sigf(v0);
        float fv = sigf(v1);
        float gv = tanhf_fast(v2);
        float ov = sigf(v3);
        c = fv * c + iv * gv;
        float* Hout = g_H + (size_t)(L * (TT + 1) + t + 1) * HB * HB;
        __stcg(Hout + (jrow >> 1) * 256 + be * 2 + (jrow & 1), ov * tanhf_fast(c));

        __syncthreads();
        if (tid == 0) strel(&g_flagsH[L * GCTA + g], t + 1);
    }
}

// ---- X body: 32 CTAs, 512 thr, warp = kq(4 x 32cols) * rh(4 x 8rows), 4 b/thread
__device__ __forceinline__ void x_run(int xl, int xg, float* Wsm, float* RDx)
{
    const int tid  = threadIdx.x;
    const int lane = tid & 31;
    const int warp = tid >> 5;
    const int rh   = warp & 3;
    const int kq   = warp >> 2;          // 0..3
    const int belo = xl;                 // below layer index = xl (0->L0, 1->L1)

    for (int i = tid; i < XR * 128; i += 512)
        Wsm[i] = g_WpX[(xl * XCTA + xg) * XR * 128 + i];
    __syncthreads();

    const int srow = tid >> 4;           // 0..31 (sum phase)
    const int sb   = (tid & 15) * 8;
    const int sR   = (srow >> 3) * 128 + xg * 8 + (srow & 7);   // global gate row

    for (int t = 0; t < TT; t++) {
        if (warp == 0) {
            const int* fl = g_flagsH + belo * GCTA;
            int f = ldacq(fl + lane);
            while (__ballot_sync(0xffffffffu, f < t + 1)) f = ldacq(fl + lane);
        }
        __syncthreads();

        const float* src = g_H + (size_t)(belo * (TT + 1) + t + 1) * HB * HB;
        const float2* f2 = reinterpret_cast<const float2*>(src);

        ull acc[32];                      // [8 rows][4 b]
        #pragma unroll
        for (int r = 0; r < 32; r++) acc[r] = 0ULL;

        #pragma unroll
        for (int kk = 0; kk < 32; kk += 4) {
            int jp = (kq * 32 + kk) >> 1;
            ull h0[4], h1[4];
            #pragma unroll
            for (int m = 0; m < 4; m++) {
                float2 a = __ldcg(f2 + jp * 128 + lane + 32 * m);
                float2 b = __ldcg(f2 + (jp + 1) * 128 + lane + 32 * m);
                h0[m] = pk2(a.x, a.y);
                h1[m] = pk2(b.x, b.y);
            }
            const float* wrow = Wsm + kq * 32 + kk;
            #pragma unroll
            for (int r = 0; r < 8; r++) {
                ulonglong2 w = *(const ulonglong2*)(wrow + (rh * 8 + r) * 128);
                #pragma unroll
                for (int m = 0; m < 4; m++) {
                    acc[r * 4 + m] = ffma2(w.x, h0[m], acc[r * 4 + m]);
                    acc[r * 4 + m] = ffma2(w.y, h1[m], acc[r * 4 + m]);
                }
            }
        }

        #pragma unroll
        for (int r = 0; r < 8; r++)
            #pragma unroll
            for (int m = 0; m < 4; m++) {
                float lo, hi; upk2(acc[r * 4 + m], lo, hi);
                RDx[(kq * XR + rh * 8 + r) * HB + lane + 32 * m] = lo + hi;
            }
        __syncthreads();

        // sum over kq and store partials: thread owns (srow, 8 b)
        float* Pout = g_P + (((size_t)(xl + 1) * TT + t) * 512 + sR) * HB;
        float4 s0, s1;
        {
            const float* r0 = RDx + (0 * XR + srow) * HB + sb;
            const float* r1 = RDx + (1 * XR + srow) * HB + sb;
            const float* r2 = RDx + (2 * XR + srow) * HB + sb;
            const float* r3 = RDx + (3 * XR + srow) * HB + sb;
            s0.x = r0[0]+r1[0]+r2[0]+r3[0];  s0.y = r0[1]+r1[1]+r2[1]+r3[1];
            s0.z = r0[2]+r1[2]+r2[2]+r3[2];  s0.w = r0[3]+r1[3]+r2[3]+r3[3];
            s1.x = r0[4]+r1[4]+r2[4]+r3[4];  s1.y = r0[5]+r1[5]+r2[5]+r3[5];
            s1.z = r0[6]+r1[6]+r2[6]+r3[6];  s1.w = r0[7]+r1[7]+r2[7]+r3[7];
        }
        *reinterpret_cast<float4*>(Pout + sb)     = s0;
        *reinterpret_cast<float4*>(Pout + sb + 4) = s1;

        __syncthreads();   // stores done + RDx safe to overwrite
        if (tid == 0) strel(&g_flagsX[xl * XCTA + xg], t + 1);
    }
}

__global__ void __launch_bounds__(512, 1) lstm_kernel(
    const float* __restrict__ W_out, const float* __restrict__ b_out,
    float* __restrict__ out)
{
    extern __shared__ float sm[];
    const int blk = blockIdx.x;

    if (blk < NL * GCTA) {
        float* Wsm = sm;                    // 16*128 = 2048 f
        float* RD  = sm + NR * 128;         // 8*16*128 = 16384 f
        float* bsm = RD + 8 * NR * HB;      // 16 f
        const int l = blk >> 5, g = blk & 31;
        if (l == 0)      h_run<0>(g, Wsm, RD, bsm);
        else if (l == 1) h_run<1>(g, Wsm, RD, bsm);
        else             h_run<2>(g, Wsm, RD, bsm);

        // head folded into H CTA (layer2, g=0): blk == 64
        if (blk == 2 * GCTA) {
            if (threadIdx.x < 32) {
                const int* fl = g_flagsH + 2 * GCTA;
                int f = ldacq(fl + (threadIdx.x & 31));
                while (__ballot_sync(0xffffffffu, f < TT))
                    f = ldacq(fl + (threadIdx.x & 31));
            }
            __syncthreads();
            if (threadIdx.x < HB) {
                const float* h = g_H + (size_t)(2 * (TT + 1) + TT) * HB * HB;
                int b = threadIdx.x;
                float s = b_out[0];
                #pragma unroll 8
                for (int j = 0; j < HB; j++)
                    s += __ldcg(h + (j >> 1) * 256 + b * 2 + (j & 1)) * W_out[j];
                out[b] = s;
            }
        }
    } else {
        float* Wsm = sm;                    // 32*128 = 4096 f
        float* RDx = sm + XR * 128;         // 4*32*128 = 16384 f
        const int xi = blk - NL * GCTA;
        x_run(xi >> 4, xi & 15, Wsm, RDx);
    }
}

extern "C" void kernel_launch(void* const* d_in, const int* in_sizes, int n_in,
                              void* d_out, int out_size)
{
    (void)in_sizes; (void)n_in; (void)out_size;

    const int SMEM_DYN = (XR * 128 + 4 * XR * HB) * 4 + 256;   // 82,176 B
    cudaFuncSetAttribute(lstm_kernel,
                         cudaFuncAttributeMaxDynamicSharedMemorySize, SMEM_DYN);

    setup_kernel<<<NL * GCTA + 2 * XCTA + TT + NL + 1, 512>>>(
        (const float*)d_in[0],
        (const float*)d_in[1], (const float*)d_in[2],
        (const float*)d_in[3], (const float*)d_in[4],
        (const float*)d_in[5], (const float*)d_in[6],
        (const float*)d_in[7], (const float*)d_in[8],
        (const float*)d_in[9], (const float*)d_in[10],
        (const float*)d_in[11], (const float*)d_in[12]);
    lstm_kernel<<<NL * GCTA + 2 * XCTA, 512, SMEM_DYN>>>(
        (const float*)d_in[13], (const float*)d_in[14], (float*)d_out);
}

// round 14
// speedup vs baseline: 1.3461x; 1.3461x over previous
#include <cuda_runtime.h>
#include <cstdio>

#define TT   2048
#define HB   128
#define NL   3
#define GCTA 32
#define NJ   4
#define NR   16

// Layer 0: K = 8(pad) + 128 = 136 ; layers 1,2: K = 256
#define WOFF0 0
#define WOFF1 (GCTA*NR*136)
#define WOFF2 (WOFF1 + GCTA*NR*256)
#define WTOT  (WOFF2 + GCTA*NR*256)

// h history, PAIR-PACKED: (l, slot, j, b) at ((l*(TT+1)+slot)*64 + (j>>1))*256 + b*2 + (j&1)
__device__ __align__(16) float g_H[(size_t)NL * (TT + 1) * HB * HB];
// x transposed, pair-packed: (t, i, b) at (t*4 + (i>>1))*256 + b*2 + (i&1), i pad 6->8
__device__ __align__(16) float g_xT[TT * 8 * HB];
__device__ float g_Wp[WTOT];
__device__ float g_bias[NL * GCTA * NR];
// One monotonic flag per (layer, producer CTA) = completed steps. 32 flags = one line.
__device__ __align__(128) int g_flags[NL * GCTA];

typedef unsigned long long ull;

__device__ __forceinline__ ull pk2(float lo, float hi) {
    ull r; asm("mov.b64 %0,{%1,%2};" : "=l"(r) : "f"(lo), "f"(hi)); return r;
}
__device__ __forceinline__ void upk2(ull v, float& lo, float& hi) {
    asm("mov.b64 {%0,%1},%2;" : "=f"(lo), "=f"(hi) : "l"(v));
}
__device__ __forceinline__ ull ffma2(ull a, ull b, ull c) {
    ull d; asm("fma.rn.f32x2 %0,%1,%2,%3;" : "=l"(d) : "l"(a), "l"(b), "l"(c));
    return d;
}
__device__ __forceinline__ int ldacq(const int* p) {
    int v; asm volatile("ld.acquire.gpu.global.b32 %0,[%1];" : "=r"(v) : "l"(p) : "memory");
    return v;
}
__device__ __forceinline__ void strel(int* p, int v) {
    asm volatile("st.release.gpu.global.b32 [%0],%1;" :: "l"(p), "r"(v) : "memory");
}
__device__ __forceinline__ float sigf(float x) {
    return __fdividef(1.0f, 1.0f + __expf(-x));
}
__device__ __forceinline__ float tanhf_fast(float x) {
    return __fdividef(2.0f, 1.0f + __expf(-2.0f * x)) - 1.0f;
}
// Warp-collective single-line wait (ONE warp calls): lane i checks fl[i] >= t.
__device__ __forceinline__ void spin1(const int* fl, int t, int lane) {
    int f = ldacq(fl + lane);
    while (__ballot_sync(0xffffffffu, f < t) != 0u) f = ldacq(fl + lane);
}

// ============ setup: pack weights/bias + transpose x + zero state ============
__global__ void setup_kernel(
    const float* __restrict__ x,
    const float* __restrict__ Wih0, const float* __restrict__ Whh0,
    const float* __restrict__ bih0, const float* __restrict__ bhh0,
    const float* __restrict__ Wih1, const float* __restrict__ Whh1,
    const float* __restrict__ bih1, const float* __restrict__ bhh1,
    const float* __restrict__ Wih2, const float* __restrict__ Whh2,
    const float* __restrict__ bih2, const float* __restrict__ bhh2)
{
    int blk = blockIdx.x, tid = threadIdx.x;
    if (blk < NL * GCTA) {
        int l = blk / GCTA, g = blk % GCTA;
        const float* Wih = (l == 0) ? Wih0 : ((l == 1) ? Wih1 : Wih2);
        const float* Whh = (l == 0) ? Whh0 : ((l == 1) ? Whh1 : Whh2);
        const float* bih = (l == 0) ? bih0 : ((l == 1) ? bih1 : bih2);
        const float* bhh = (l == 0) ? bhh0 : ((l == 1) ? bhh1 : bhh2);
        int KA = (l == 0) ? 8 : 128;
        int KP = KA + 128;
        int base = ((l == 0) ? WOFF0 : ((l == 1) ? WOFF1 : WOFF2)) + g * NR * KP;
        for (int idx = tid; idx < NR * KP; idx += blockDim.x) {
            int r = idx / KP, k = idx % KP;
            int q = r >> 2, jj = r & 3;
            int R = q * 128 + (g * NJ + jj);
            float v;
            if (k < KA) v = (l == 0) ? ((k < 6) ? Wih[R * 6 + k] : 0.0f)
                                     : Wih[R * 128 + k];
            else        v = Whh[R * 128 + (k - KA)];
            g_Wp[base + idx] = v;
        }
        if (tid < NR) {
            int r = tid, q = r >> 2, jj = r & 3;
            int R = q * 128 + (g * NJ + jj);
            g_bias[(l * GCTA + g) * NR + r] = bih[R] + bhh[R];
        }
        if (blk == 0 && tid < NL * GCTA) g_flags[tid] = 0;
    } else if (blk < NL * GCTA + TT) {
        int t = blk - NL * GCTA;
        if (tid < HB) {
            #pragma unroll
            for (int i = 0; i < 8; i++) {
                float v = (i < 6) ? x[(size_t)tid * (TT * 6) + t * 6 + i] : 0.0f;
                g_xT[(t * 4 + (i >> 1)) * 256 + tid * 2 + (i & 1)] = v;
            }
        }
    } else {
        size_t base = (size_t)(blk - NL * GCTA - TT) * (TT + 1) * HB * HB;
        for (int i = tid; i < HB * HB; i += blockDim.x) g_H[base + i] = 0.0f;
    }
}

// ---- GEMM, 16 packed cols, pair-packed src, 2 batch cols per thread.
// FRONT-BATCHED: all 16 LDG.64 issued first (MLP 16), then the FFMA block.
template<int KP>
__device__ __forceinline__ void gemm16_2b(const float* __restrict__ src,
                                          const float* __restrict__ Wsm,
                                          int S, int J, int b0, ull* acc /*32*/)
{
    const float2* f2 = reinterpret_cast<const float2*>(src);
    ull h[8], gg[8];
    #pragma unroll
    for (int kk = 0; kk < 16; kk += 2) {
        int jp = (J + kk) >> 1;
        float2 a = __ldcg(f2 + jp * 128 + b0);
        float2 e = __ldcg(f2 + jp * 128 + b0 + 32);
        h[kk >> 1]  = pk2(a.x, a.y);
        gg[kk >> 1] = pk2(e.x, e.y);
    }
    #pragma unroll
    for (int kk = 0; kk < 16; kk += 4) {
        const float* wrow = Wsm + S + kk;
        ull h01 = h[kk >> 1], h23 = h[(kk >> 1) + 1];
        ull g01 = gg[kk >> 1], g23 = gg[(kk >> 1) + 1];
        #pragma unroll
        for (int r = 0; r < NR; r++) {
            ulonglong2 w = *(const ulonglong2*)(wrow + r * KP); // LDS.128 bcast
            acc[r]      = ffma2(w.x, h01, acc[r]);
            acc[r]      = ffma2(w.y, h23, acc[r]);
            acc[NR + r] = ffma2(w.x, g01, acc[NR + r]);
            acc[NR + r] = ffma2(w.y, g23, acc[NR + r]);
        }
    }
}

// ---- 2-col slice (layer-0 input part)
template<int KP>
__device__ __forceinline__ void gemm2_2b(const float* __restrict__ src,
                                         const float* __restrict__ Wsm,
                                         int S, int b0, ull* acc)
{
    const float2* f2 = reinterpret_cast<const float2*>(src);
    float2 a = __ldcg(f2 + (S >> 1) * 128 + b0);
    float2 e = __ldcg(f2 + (S >> 1) * 128 + b0 + 32);
    ull h01 = pk2(a.x, a.y), g01 = pk2(e.x, e.y);
    #pragma unroll
    for (int r = 0; r < NR; r++) {
        ull w = *(const ull*)(Wsm + S + r * KP);
        acc[r]      = ffma2(w, h01, acc[r]);
        acc[NR + r] = ffma2(w, g01, acc[NR + r]);
    }
}

// ---- per-layer persistent body, 512 threads (16 warps), 1 CTA/SM.
// Phase order: [spin below] -> SA gemm -> [spin own] -> SB gemm -> reduce -> epi.
template<int L>
__device__ __forceinline__ void lstm_run(int g, float* Wsm, float* RD, float* bsm)
{
    constexpr int KA = (L == 0) ? 8 : 128;
    constexpr int KP = KA + 128;
    constexpr int WOFF = (L == 0) ? WOFF0 : ((L == 1) ? WOFF1 : WOFF2);

    const int tid  = threadIdx.x;
    const int lane = tid & 31;
    const int warp = tid >> 5;
    const int bg   = warp & 1;
    const int kq   = warp >> 1;
    const int b0   = bg * 64 + lane;
    const int jj   = tid >> 7;
    const int be   = tid & 127;
    const int jrow = g * NJ + jj;

    const int wbase = WOFF + g * NR * KP;
    for (int i = tid; i < NR * KP; i += 512) Wsm[i] = g_Wp[wbase + i];
    if (tid < NR) bsm[tid] = g_bias[(L * GCTA + g) * NR + tid];
    __syncthreads();

    float c = 0.0f;

    // phase-cycle accumulators (tid 0 only; printed once at the end)
    long long aSpinA = 0, aSA = 0, aSpinB = 0, aSB = 0, aRed = 0, aEpi = 0;
    long long tP = clock64();

    for (int t = 0; t < TT; t++) {
        // ---- wait for below-layer h(t)
        if (L > 0) {
            if (warp == 0) spin1(g_flags + (L - 1) * GCTA, t + 1, lane);
            __syncthreads();
        }
        if (tid == 0) { long long n = clock64(); aSpinA += n - tP; tP = n; }

        const float* SA = (L == 0)
            ? (g_xT + (size_t)t * 4 * 256)
            : (g_H + (size_t)((L - 1) * (TT + 1) + t + 1) * HB * HB);

        ull acc[2 * NR];
        #pragma unroll
        for (int r = 0; r < 2 * NR; r++) acc[r] = 0ULL;

        // ---- SA gemm (own-layer flag NOT needed yet)
        if constexpr (L == 0) {
            if (kq < 4) gemm2_2b<KP>(SA, Wsm, kq * 2, b0, acc);
        } else {
            gemm16_2b<KP>(SA, Wsm, kq * 16, kq * 16, b0, acc);
        }
        if (tid == 0) { long long n = clock64(); aSA += n - tP; tP = n; }

        // ---- wait for own-layer h(t-1)
        if (t > 0) {
            if (warp == 0) spin1(g_flags + L * GCTA, t, lane);
            __syncthreads();
        }
        if (tid == 0) { long long n = clock64(); aSpinB += n - tP; tP = n; }

        const float* SB = g_H + (size_t)(L * (TT + 1) + t) * HB * HB;
        gemm16_2b<KP>(SB, Wsm, KA + kq * 16, kq * 16, b0, acc);
        if (tid == 0) { long long n = clock64(); aSB += n - tP; tP = n; }

        #pragma unroll
        for (int r = 0; r < NR; r++) {
            float lo, hi; upk2(acc[r], lo, hi);
            RD[(kq * NR + r) * HB + b0] = lo + hi;
            upk2(acc[NR + r], lo, hi);
            RD[(kq * NR + r) * HB + b0 + 32] = lo + hi;
        }
        __syncthreads();
        if (tid == 0) { long long n = clock64(); aRed += n - tP; tP = n; }

        // ---- epilogue: all 512 threads, one (jj, be) each
        {
            float v0 = bsm[0 * NJ + jj], v1 = bsm[1 * NJ + jj];
            float v2 = bsm[2 * NJ + jj], v3 = bsm[3 * NJ + jj];
            #pragma unroll
            for (int q2 = 0; q2 < 8; q2++) {
                v0 += RD[(q2 * NR + 0 * NJ + jj) * HB + be];
                v1 += RD[(q2 * NR + 1 * NJ + jj) * HB + be];
                v2 += RD[(q2 * NR + 2 * NJ + jj) * HB + be];
                v3 += RD[(q2 * NR + 3 * NJ + jj) * HB + be];
            }
            float iv = sigf(v0);
            float fv = sigf(v1);
            float gv = tanhf_fast(v2);
            float ov = sigf(v3);
            c = fv * c + iv * gv;
            float* Hout = g_H + (size_t)(L * (TT + 1) + t + 1) * HB * HB;
            __stcg(Hout + (jrow >> 1) * 256 + be * 2 + (jrow & 1),
                   ov * tanhf_fast(c));
        }
        __syncthreads();   // all h stores program-ordered before the release
        if (tid == 0) {
            strel(&g_flags[L * GCTA + g], t + 1);
            long long n = clock64(); aEpi += n - tP; tP = n;
        }
    }

    if (tid == 0 && g == 0) {
        printf("PHASES L%d spinA=%lld sa=%lld spinB=%lld sb=%lld red=%lld epi=%lld (cyc/step)\n",
               L, aSpinA / TT, aSA / TT, aSpinB / TT, aSB / TT, aRed / TT, aEpi / TT);
    }
}

__global__ void __launch_bounds__(512, 1) lstm_kernel(
    const float* __restrict__ W_out, const float* __restrict__ b_out,
    float* __restrict__ out)
{
    extern __shared__ float sm[];
    float* Wsm = sm;                       // NR*256 floats (16 KB)
    float* RD  = sm + NR * 256;            // 8*NR*HB floats (64 KB)
    float* bsm = RD + 8 * NR * HB;         // NR floats

    const int blk = blockIdx.x;
    const int l = blk >> 5, g = blk & 31;
    if (l == 0)      lstm_run<0>(g, Wsm, RD, bsm);
    else if (l == 1) lstm_run<1>(g, Wsm, RD, bsm);
    else             lstm_run<2>(g, Wsm, RD, bsm);

    // ---- head folded into CTA 64 (layer 2, g = 0)
    if (blk == 2 * GCTA) {
        if (threadIdx.x < 32) spin1(g_flags + 2 * GCTA, TT, threadIdx.x & 31);
        __syncthreads();
        if (threadIdx.x < HB) {
            const float* h = g_H + (size_t)(2 * (TT + 1) + TT) * HB * HB;
            int b = threadIdx.x;
            float s = b_out[0];
            #pragma unroll 8
            for (int j = 0; j < HB; j++)
                s += __ldcg(h + (j >> 1) * 256 + b * 2 + (j & 1)) * W_out[j];
            out[b] = s;
        }
    }
}

extern "C" void kernel_launch(void* const* d_in, const int* in_sizes, int n_in,
                              void* d_out, int out_size)
{
    (void)in_sizes; (void)n_in; (void)out_size;

    const int SMEM_DYN = (NR * 256 + 8 * NR * HB + NR) * 4;   // 80,960 B
    cudaFuncSetAttribute(lstm_kernel,
                         cudaFuncAttributeMaxDynamicSharedMemorySize, SMEM_DYN);

    setup_kernel<<<NL * GCTA + TT + NL, 256>>>(
        (const float*)d_in[0],
        (const float*)d_in[1], (const float*)d_in[2],
        (const float*)d_in[3], (const float*)d_in[4],
        (const float*)d_in[5], (const float*)d_in[6],
        (const float*)d_in[7], (const float*)d_in[8],
        (const float*)d_in[9], (const float*)d_in[10],
        (const float*)d_in[11], (const float*)d_in[12]);
    lstm_kernel<<<NL * GCTA, 512, SMEM_DYN>>>(
        (const float*)d_in[13], (const float*)d_in[14], (float*)d_out);
}